// round 13
// baseline (speedup 1.0000x reference)
#include <cuda_runtime.h>
#include <cuda_fp16.h>
#include <cstdint>

#define NS 200000
#define NA 400000
#define NU 200000
#define HH 64
#define ESS 2000000
#define EAS 4000000
#define EUS 2000000
#define NB 196                 // ceil(NS/1024) scan blocks
#define GEMM_TILES 3125        // NS/64

// smem layout (bytes):
//   Ws  half[256][72]  36864   @ 0
//   As  half[256][72]  36864   @ 36864   (4 relations x 64 rows; aliased by Hs f32[64][68])
//   Bs  f32[64]          256   @ 73728
//   Wfs f32[384]        1536   @ 73984
//   bfs f32[8]            32   @ 75520
#define SMEM_WS   0
#define SMEM_AS   36864
#define SMEM_BS   73728
#define SMEM_WFS  73984
#define SMEM_BFS  75520
#define GEMM_SMEM 75552

typedef unsigned long long ull;

// ---------------- static device scratch (no allocations allowed) ----------------
__device__ __align__(256) __half h_sub[NS*HH];
__device__ __align__(256) __half h_agr[NA*HH];
__device__ __align__(256) __half h_urb[NU*HH];
__device__ __align__(256) __half g_agg_ss[NS*HH];
__device__ __align__(256) __half g_agg_as[NS*HH];
__device__ __align__(256) __half g_agg_us[NS*HH];
__device__ __align__(256) __half g_sub0[NS*HH];
__device__ __align__(256) __half g_sub1[NS*HH];
__device__ int g_csr_ss[ESS];
__device__ int g_csr_as[EAS];
__device__ int g_csr_us[EUS];
__device__ int g_off_ss[NS+1];
__device__ int g_off_as[NS+1];
__device__ int g_off_us[NS+1];
__device__ int g_cur_ss[NS];
__device__ int g_cur_as[NS];
__device__ int g_cur_us[NS];
__device__ int g_part[3*256];
__device__ __align__(16) __half g_Wh[3*4*HH*HH];   // [layer][r*64+k][o] fp16
__device__ float g_bias[3*HH];

// ---------------- helpers ----------------
__device__ __forceinline__ int* rel_cur(int rel){ return rel==0? g_cur_ss : rel==1? g_cur_as : g_cur_us; }
__device__ __forceinline__ int* rel_off(int rel){ return rel==0? g_off_ss : rel==1? g_off_as : g_off_us; }
__device__ __forceinline__ int* rel_csr(int rel){ return rel==0? g_csr_ss : rel==1? g_csr_as : g_csr_us; }

__device__ __forceinline__ void ldsm_x4(uint32_t& r0, uint32_t& r1, uint32_t& r2, uint32_t& r3, uint32_t addr){
    asm volatile("ldmatrix.sync.aligned.m8n8.x4.shared.b16 {%0,%1,%2,%3}, [%4];"
        : "=r"(r0),"=r"(r1),"=r"(r2),"=r"(r3) : "r"(addr));
}
__device__ __forceinline__ void ldsm_x4_t(uint32_t& r0, uint32_t& r1, uint32_t& r2, uint32_t& r3, uint32_t addr){
    asm volatile("ldmatrix.sync.aligned.m8n8.x4.trans.shared.b16 {%0,%1,%2,%3}, [%4];"
        : "=r"(r0),"=r"(r1),"=r"(r2),"=r"(r3) : "r"(addr));
}
__device__ __forceinline__ void mma16816(float* c, uint32_t a0,uint32_t a1,uint32_t a2,uint32_t a3,
                                         uint32_t b0, uint32_t b1){
    asm volatile("mma.sync.aligned.m16n8k16.row.col.f32.f16.f16.f32 "
                 "{%0,%1,%2,%3},{%4,%5,%6,%7},{%8,%9},{%0,%1,%2,%3};"
        : "+f"(c[0]),"+f"(c[1]),"+f"(c[2]),"+f"(c[3])
        : "r"(a0),"r"(a1),"r"(a2),"r"(a3),"r"(b0),"r"(b1));
}

// ---------------- init: build fp16 weights [layer][r*64+k][o] + fused bias + zero cursors ----------------
__global__ void k_init(const float* __restrict__ Wl, const float* __restrict__ bl,
                       const float* __restrict__ Wr)
{
    for (int idx = blockIdx.x*blockDim.x + threadIdx.x; idx < 3*4*64*64; idx += gridDim.x*blockDim.x){
        int o = idx & 63;
        int k = (idx>>6) & 63;
        int r = (idx>>12) & 3;
        int l = idx>>14;
        float w;
        if (r < 3) w = Wl[(((size_t)l*3 + r)*64 + o)*64 + k];
        else       w = Wr[(((size_t)l*3 + 0)*64 + o)*64 + k]
                     + Wr[(((size_t)l*3 + 1)*64 + o)*64 + k]
                     + Wr[(((size_t)l*3 + 2)*64 + o)*64 + k];
        g_Wh[idx] = __float2half(w);
        if (idx < 3*64){
            int l2 = idx>>6, o2 = idx&63;
            g_bias[idx] = bl[(l2*3+0)*64+o2] + bl[(l2*3+1)*64+o2] + bl[(l2*3+2)*64+o2];
        }
    }
    for (int i = blockIdx.x*blockDim.x + threadIdx.x; i < NS; i += gridDim.x*blockDim.x){
        g_cur_ss[i]=0; g_cur_as[i]=0; g_cur_us[i]=0;
    }
}

// ---------------- fp32 -> fp16 conversion of node features ----------------
__global__ void k_convert(const float* __restrict__ xs, const float* __restrict__ xa,
                          const float* __restrict__ xu)
{
    int b = blockIdx.x;
    const float4* src; uint2* dst; int n4, b0, nb;
    if (b < 2048){ src=(const float4*)xs; dst=(uint2*)h_sub; n4=NS*16; b0=0;    nb=2048; }
    else if (b < 6144){ src=(const float4*)xa; dst=(uint2*)h_agr; n4=NA*16; b0=2048; nb=4096; }
    else { src=(const float4*)xu; dst=(uint2*)h_urb; n4=NU*16; b0=6144; nb=2048; }
    for (int i = (b-b0)*blockDim.x + threadIdx.x; i < n4; i += nb*blockDim.x){
        float4 v = __ldg(&src[i]);
        __half2 h0 = __floats2half2_rn(v.x, v.y);
        __half2 h1 = __floats2half2_rn(v.z, v.w);
        uint2 u;
        u.x = *(unsigned*)&h0;
        u.y = *(unsigned*)&h1;
        dst[i] = u;
    }
}

// ---------------- merged CSR count ----------------
__global__ void k_count_all(const int* __restrict__ d_ss, const int* __restrict__ d_as,
                            const int* __restrict__ d_us)
{
    int b = blockIdx.x;
    const int* dst; int E, b0, nb; int* cur;
    if (b < 2048){ dst=d_ss; E=ESS; b0=0;    nb=2048; cur=g_cur_ss; }
    else if (b < 6144){ dst=d_as; E=EAS; b0=2048; nb=4096; cur=g_cur_as; }
    else { dst=d_us; E=EUS; b0=6144; nb=2048; cur=g_cur_us; }
    for (int e = (b-b0)*blockDim.x + threadIdx.x; e < E; e += nb*blockDim.x)
        atomicAdd(&cur[__ldg(&dst[e])], 1);
}

// ---------------- merged scans ----------------
__global__ void k_scan_local_all()
{
    int rel = blockIdx.x / NB;
    int blk = blockIdx.x % NB;
    const int* deg = rel_cur(rel);
    int* off = rel_off(rel);
    int* part = g_part + rel*256;
    __shared__ int s[2][1024];
    int t = threadIdx.x;
    int i = blk*1024 + t;
    int v = (i < NS) ? deg[i] : 0;
    int pa = 0;
    s[0][t] = v;
    __syncthreads();
    #pragma unroll
    for (int d = 1; d < 1024; d <<= 1){
        int val = s[pa][t];
        if (t >= d) val += s[pa][t-d];
        s[pa^1][t] = val;
        pa ^= 1;
        __syncthreads();
    }
    int inc = s[pa][t];
    if (i < NS) off[i] = inc - v;        // block-local exclusive
    if (t == 1023) part[blk] = inc;
}

__global__ void k_scan_part_all()
{
    int rel = blockIdx.x;
    int* part = g_part + rel*256;
    int* off = rel_off(rel);
    __shared__ int ws[8];
    int t = threadIdx.x;
    int lane = t & 31, wid = t >> 5;
    int v = (t < NB) ? part[t] : 0;
    int x = v;
    #pragma unroll
    for (int d = 1; d < 32; d <<= 1){
        int y = __shfl_up_sync(0xffffffffu, x, d);
        if (lane >= d) x += y;
    }
    if (lane == 31) ws[wid] = x;
    __syncthreads();
    if (t == 0){
        int run = 0;
        #pragma unroll
        for (int i = 0; i < 8; i++){ int tmp = ws[i]; ws[i] = run; run += tmp; }
    }
    __syncthreads();
    x += ws[wid];
    if (t < NB) part[t] = x - v;         // exclusive partials
    if (t == 255) off[NS] = x;           // grand total
}

__global__ void k_scan_add_all()
{
    int rel = blockIdx.x / NB;
    int blk = blockIdx.x % NB;
    int* off = rel_off(rel);
    int* cur = rel_cur(rel);
    const int* part = g_part + rel*256;
    int i = blk*1024 + threadIdx.x;
    if (i < NS){
        int v = off[i] + part[blk];
        off[i] = v;
        cur[i] = v;       // cursor for fill
    }
}

// ---------------- merged fill ----------------
__global__ void k_fill_all(const int* __restrict__ ss_s, const int* __restrict__ ss_d,
                           const int* __restrict__ as_s, const int* __restrict__ as_d,
                           const int* __restrict__ us_s, const int* __restrict__ us_d)
{
    int b = blockIdx.x;
    const int* src; const int* dst; int E, b0, nb; int* cur; int* csr;
    if (b < 2048){ src=ss_s; dst=ss_d; E=ESS; b0=0;    nb=2048; cur=g_cur_ss; csr=g_csr_ss; }
    else if (b < 6144){ src=as_s; dst=as_d; E=EAS; b0=2048; nb=4096; cur=g_cur_as; csr=g_csr_as; }
    else { src=us_s; dst=us_d; E=EUS; b0=6144; nb=2048; cur=g_cur_us; csr=g_csr_us; }
    for (int e = (b-b0)*blockDim.x + threadIdx.x; e < E; e += nb*blockDim.x){
        int d = __ldg(&dst[e]);
        int p = atomicAdd(&cur[d], 1);
        csr[p] = __ldg(&src[e]);
    }
}

// ---------------- gather core: one node per warp, 32 lanes x half2, shfl-broadcast indices ----------------
// Lane l preloads csr[base+l]; inner loop shuffles index j out -> 1 LSU op per edge instead of 2.
__device__ __forceinline__ void gather_sum_h(const __half2* __restrict__ x2,
                                             const int* __restrict__ csr,
                                             int b, int e, int lane,
                                             float& ax, float& ay)
{
    for (int base = b; base < e; base += 32){
        int n = e - base; if (n > 32) n = 32;
        int pre = lane; if (pre > n-1) pre = n-1;
        int idx = __ldg(&csr[base + pre]);
        int j = 0;
        #pragma unroll 4
        for (; j + 4 <= n; j += 4){
            int s0 = __shfl_sync(0xffffffffu, idx, j);
            int s1 = __shfl_sync(0xffffffffu, idx, j+1);
            int s2 = __shfl_sync(0xffffffffu, idx, j+2);
            int s3 = __shfl_sync(0xffffffffu, idx, j+3);
            float2 f0 = __half22float2(__ldg(&x2[(size_t)s0*32 + lane]));
            float2 f1 = __half22float2(__ldg(&x2[(size_t)s1*32 + lane]));
            float2 f2 = __half22float2(__ldg(&x2[(size_t)s2*32 + lane]));
            float2 f3 = __half22float2(__ldg(&x2[(size_t)s3*32 + lane]));
            ax += (f0.x + f1.x) + (f2.x + f3.x);
            ay += (f0.y + f1.y) + (f2.y + f3.y);
        }
        for (; j < n; j++){
            int s0 = __shfl_sync(0xffffffffu, idx, j);
            float2 f0 = __half22float2(__ldg(&x2[(size_t)s0*32 + lane]));
            ax += f0.x; ay += f0.y;
        }
    }
}

// external-feature gather (sum): one warp per destination node; one relation per launch
__global__ void k_gather_ext(int rel, int outsel)
{
    int warp = (blockIdx.x*blockDim.x + threadIdx.x) >> 5;
    int lane = threadIdx.x & 31;
    if (warp >= NS) return;
    const __half* x = rel==0 ? h_sub : (rel==1 ? h_agr : h_urb);
    const int* csr = rel_csr(rel);
    const int* off = rel_off(rel);
    __half* op = outsel==0 ? g_agg_ss : (outsel==1 ? g_agg_as : g_agg_us);
    int b = __ldg(&off[warp]);
    int e = __ldg(&off[warp+1]);
    float ax = 0.f, ay = 0.f;
    gather_sum_h((const __half2*)x, csr, b, e, lane, ax, ay);
    ((__half2*)op)[(size_t)warp*32 + lane] = __floats2half2_rn(ax, ay);
}

// per-layer ss gather with mean (layers 1,2)
__global__ void k_gather_ss(int insel)
{
    const __half* x = insel==1 ? g_sub0 : g_sub1;
    int warp = (blockIdx.x*blockDim.x + threadIdx.x) >> 5;
    int lane = threadIdx.x & 31;
    if (warp >= NS) return;
    int b = __ldg(&g_off_ss[warp]);
    int e = __ldg(&g_off_ss[warp+1]);
    float ax = 0.f, ay = 0.f;
    gather_sum_h((const __half2*)x, g_csr_ss, b, e, lane, ax, ay);
    if (e > b){ float sc = 1.f/(float)(e-b); ax *= sc; ay *= sc; }
    ((__half2*)g_agg_ss)[(size_t)warp*32 + lane] = __floats2half2_rn(ax, ay);
}

// ---------------- fused layer GEMM on tensor cores (+ optional softmax head epilogue) ----------------
__global__ void __launch_bounds__(256,2)
k_gemm(int sub_sel, int out_sel, int layer,
       const float* __restrict__ Wf, const float* __restrict__ bf,
       float* __restrict__ outhead, int do_head)
{
    extern __shared__ char sm[];
    __half* Ws  = (__half*)(sm + SMEM_WS);
    __half* As  = (__half*)(sm + SMEM_AS);
    float*  Bs  = (float*)(sm + SMEM_BS);
    float*  Wfs = (float*)(sm + SMEM_WFS);
    float*  bfs = (float*)(sm + SMEM_BFS);

    const int tid  = threadIdx.x;
    const int lane = tid & 31;
    const int warp = tid >> 5;
    const int wm   = warp & 3;          // m-block: rows wm*16..+15
    const int wn   = warp >> 2;         // n-block: cols wn*32..+31

    // stage weights (once): g_Wh[layer][row][o] -> Ws[row][72]
    {
        const __half* wsrc = g_Wh + layer*16384;
        #pragma unroll
        for (int it = 0; it < 8; it++){
            int chunk = it*256 + tid;           // 2048 chunks of 8 halves
            int row = chunk >> 3, c = chunk & 7;
            *(uint4*)(Ws + row*72 + c*8) = *(const uint4*)(wsrc + row*64 + c*8);
        }
    }
    if (tid < 64) Bs[tid] = g_bias[layer*64 + tid];
    if (do_head){
        for (int j = tid; j < 384; j += 256) Wfs[j] = Wf[j];
        if (tid < 6) bfs[tid] = bf[tid];
    }

    const __half* Asub = sub_sel==0 ? h_sub : (sub_sel==1 ? g_sub0 : g_sub1);
    __half* outp = out_sel==0 ? g_sub0 : g_sub1;

    // per-lane ldmatrix address components
    const int l8  = lane & 7;
    const int grp = lane >> 3;
    const int row_off = l8 + ((grp & 1) << 3);      // 0..15
    const int col_off = (grp & 2) << 2;             // 0 or 8
    const uint32_t as_base = (uint32_t)__cvta_generic_to_shared(As);
    const uint32_t ws_base = (uint32_t)__cvta_generic_to_shared(Ws);
    const uint32_t uA0 = as_base + (wm*16 + row_off)*144 + col_off*2;
    const uint32_t uB0 = ws_base + row_off*144 + (wn*32 + col_off)*2;

    for (int tile = blockIdx.x; tile < GEMM_TILES; tile += gridDim.x){
        const int base = tile*64;

        __syncthreads();   // previous tile's As/Hs readers done (also covers Ws init on tile 0)
        // stage A: 4 relations x 64 rows x 64 halves
        #pragma unroll
        for (int r = 0; r < 4; r++){
            const __half* A = (r==0) ? g_agg_ss : (r==1) ? g_agg_as : (r==2) ? g_agg_us : Asub;
            #pragma unroll
            for (int it = 0; it < 2; it++){
                int chunk = it*256 + tid;       // 512 chunks of 8 halves
                int m = chunk >> 3, c = chunk & 7;
                *(uint4*)(As + (r*64 + m)*72 + c*8) =
                    *(const uint4*)(A + ((size_t)(base + m))*64 + c*8);
            }
        }
        __syncthreads();

        float c0[4], c1[4], c2[4], c3[4];
        #pragma unroll
        for (int t = 0; t < 4; t++){ c0[t]=0.f; c1[t]=0.f; c2[t]=0.f; c3[t]=0.f; }

        #pragma unroll
        for (int ks = 0; ks < 16; ks++){
            const int r  = ks >> 2;
            const int kk = (ks & 3) << 4;
            uint32_t a0,a1,a2,a3;
            ldsm_x4(a0,a1,a2,a3, uA0 + r*9216 + kk*2);
            uint32_t b0,b1,b2,b3, b4,b5,b6,b7;
            ldsm_x4_t(b0,b1,b2,b3, uB0 + ks*2304);          // n-cols wn*32 .. +15
            ldsm_x4_t(b4,b5,b6,b7, uB0 + ks*2304 + 32);     // n-cols wn*32+16 .. +31
            mma16816(c0, a0,a1,a2,a3, b0,b1);
            mma16816(c1, a0,a1,a2,a3, b2,b3);
            mma16816(c2, a0,a1,a2,a3, b4,b5);
            mma16816(c3, a0,a1,a2,a3, b6,b7);
        }

        const int mrow = wm*16 + (lane >> 2);
        const int ncol = wn*32 + ((lane & 3) << 1);
        float* cc[4] = {c0, c1, c2, c3};
        if (!do_head){
            #pragma unroll
            for (int t = 0; t < 4; t++){
                int col = ncol + t*8;
                float bb0 = Bs[col], bb1 = Bs[col+1];
                __half2 h0 = __floats2half2_rn(fmaxf(cc[t][0]+bb0,0.f), fmaxf(cc[t][1]+bb1,0.f));
                __half2 h1 = __floats2half2_rn(fmaxf(cc[t][2]+bb0,0.f), fmaxf(cc[t][3]+bb1,0.f));
                *(__half2*)(outp + ((size_t)(base+mrow  ))*64 + col) = h0;
                *(__half2*)(outp + ((size_t)(base+mrow+8))*64 + col) = h1;
            }
        } else {
            float* Hs = (float*)As;            // 64 nodes x stride 68
            __syncthreads();                   // all warps done reading As
            #pragma unroll
            for (int t = 0; t < 4; t++){
                int col = ncol + t*8;
                float bb0 = Bs[col], bb1 = Bs[col+1];
                Hs[(mrow  )*68 + col  ] = fmaxf(cc[t][0]+bb0,0.f);
                Hs[(mrow  )*68 + col+1] = fmaxf(cc[t][1]+bb1,0.f);
                Hs[(mrow+8)*68 + col  ] = fmaxf(cc[t][2]+bb0,0.f);
                Hs[(mrow+8)*68 + col+1] = fmaxf(cc[t][3]+bb1,0.f);
            }
            __syncthreads();
            int node = tid >> 2, q = tid & 3;  // 4 threads per node, 16 k each
            const float* hrow = Hs + node*68 + q*16;
            float p[6];
            #pragma unroll
            for (int o = 0; o < 6; o++) p[o] = 0.f;
            #pragma unroll
            for (int k = 0; k < 16; k++){
                float xv = hrow[k];
                #pragma unroll
                for (int o = 0; o < 6; o++) p[o] += xv * Wfs[o*64 + q*16 + k];
            }
            #pragma unroll
            for (int s = 1; s < 4; s <<= 1){
                #pragma unroll
                for (int o = 0; o < 6; o++) p[o] += __shfl_xor_sync(0xffffffffu, p[o], s);
            }
            if (q == 0){
                float m = -1e30f;
                #pragma unroll
                for (int o = 0; o < 6; o++){ p[o] += bfs[o]; m = fmaxf(m, p[o]); }
                float ssum = 0.f;
                #pragma unroll
                for (int o = 0; o < 6; o++){ p[o] = expf(p[o] - m); ssum += p[o]; }
                float inv = 1.f/ssum;
                float* op = outhead + (size_t)(base + node)*6;
                #pragma unroll
                for (int o = 0; o < 6; o++) op[o] = p[o]*inv;
            }
            // loop-top __syncthreads() protects Hs before next tile's As staging
        }
    }
}

// ---------------- launch ----------------
extern "C" void kernel_launch(void* const* d_in, const int* in_sizes, int n_in,
                              void* d_out, int out_size)
{
    const float* x_sub   = (const float*)d_in[0];
    const float* x_agr   = (const float*)d_in[1];
    const float* x_urb   = (const float*)d_in[2];
    const float* Wl      = (const float*)d_in[3];
    const float* bl      = (const float*)d_in[4];
    const float* Wr      = (const float*)d_in[5];
    const float* Wf      = (const float*)d_in[6];
    const float* bf      = (const float*)d_in[7];
    const int*   e_ss    = (const int*)d_in[8];
    const int*   e_as_s  = (const int*)d_in[9];
    const int*   e_as_d  = (const int*)d_in[10];
    const int*   e_us    = (const int*)d_in[11];
    float* out = (float*)d_out;

    cudaFuncSetAttribute(k_gemm, cudaFuncAttributeMaxDynamicSharedMemorySize, GEMM_SMEM);

    k_init<<<512,256>>>(Wl, bl, Wr);
    k_convert<<<8192,256>>>(x_sub, x_agr, x_urb);

    k_count_all<<<8192,256>>>(e_ss + ESS, e_as_d, e_us + EUS);

    k_scan_local_all<<<3*NB,1024>>>();
    k_scan_part_all<<<3,256>>>();
    k_scan_add_all<<<3*NB,1024>>>();

    k_fill_all<<<8192,256>>>(e_ss, e_ss + ESS, e_as_s, e_as_d, e_us, e_us + EUS);

    // layer-invariant aggregations, separate launches for locality
    k_gather_ext<<<25000,256>>>(1, 1);
    k_gather_ext<<<25000,256>>>(2, 2);

    // layer 0: sum aggregation, sub input = h_sub, out -> g_sub0
    k_gather_ext<<<25000,256>>>(0, 0);
    k_gemm<<<296,256,GEMM_SMEM>>>(0, 0, 0, nullptr, nullptr, nullptr, 0);
    // layer 1: mean aggregation, sub input = g_sub0, out -> g_sub1
    k_gather_ss<<<25000,256>>>(1);
    k_gemm<<<296,256,GEMM_SMEM>>>(1, 1, 1, nullptr, nullptr, nullptr, 0);
    // layer 2: mean aggregation, sub input = g_sub1, head fused -> d_out
    k_gather_ss<<<25000,256>>>(2);
    k_gemm<<<296,256,GEMM_SMEM>>>(2, 0, 2, Wf, bf, out, 1);
}

// round 14
// speedup vs baseline: 1.3664x; 1.3664x over previous
#include <cuda_runtime.h>
#include <cuda_fp16.h>
#include <cstdint>

#define NS 200000
#define NA 400000
#define NU 200000
#define HH 64
#define ESS 2000000
#define EAS 4000000
#define EUS 2000000
#define NB 196                 // ceil(NS/1024) scan blocks
#define GEMM_TILES 3125        // NS/64

// smem layout (bytes):
//   Ws  half[256][72]  36864   @ 0
//   As  half[256][72]  36864   @ 36864   (4 relations x 64 rows; aliased by Hs f32[64][68])
//   Bs  f32[64]          256   @ 73728
//   Wfs f32[384]        1536   @ 73984
//   bfs f32[8]            32   @ 75520
#define SMEM_WS   0
#define SMEM_AS   36864
#define SMEM_BS   73728
#define SMEM_WFS  73984
#define SMEM_BFS  75520
#define GEMM_SMEM 75552

typedef unsigned long long ull;

// ---------------- static device scratch (no allocations allowed) ----------------
__device__ __align__(256) __half h_sub[NS*HH];
__device__ __align__(256) __half h_agr[NA*HH];
__device__ __align__(256) __half h_urb[NU*HH];
__device__ __align__(256) __half g_agg_ss[NS*HH];
__device__ __align__(256) __half g_agg_as[NS*HH];
__device__ __align__(256) __half g_agg_us[NS*HH];
__device__ __align__(256) __half g_sub0[NS*HH];
__device__ __align__(256) __half g_sub1[NS*HH];
__device__ int g_csr_ss[ESS];
__device__ int g_csr_as[EAS];
__device__ int g_csr_us[EUS];
__device__ int g_off_ss[NS+1];
__device__ int g_off_as[NS+1];
__device__ int g_off_us[NS+1];
__device__ int g_cur_ss[NS];
__device__ int g_cur_as[NS];
__device__ int g_cur_us[NS];
__device__ int g_part[3*256];
__device__ __align__(16) __half g_Wh[3*4*HH*HH];   // [layer][r*64+k][o] fp16
__device__ float g_bias[3*HH];

// ---------------- helpers ----------------
__device__ __forceinline__ int* rel_cur(int rel){ return rel==0? g_cur_ss : rel==1? g_cur_as : g_cur_us; }
__device__ __forceinline__ int* rel_off(int rel){ return rel==0? g_off_ss : rel==1? g_off_as : g_off_us; }
__device__ __forceinline__ int* rel_csr(int rel){ return rel==0? g_csr_ss : rel==1? g_csr_as : g_csr_us; }

__device__ __forceinline__ void ldsm_x4(uint32_t& r0, uint32_t& r1, uint32_t& r2, uint32_t& r3, uint32_t addr){
    asm volatile("ldmatrix.sync.aligned.m8n8.x4.shared.b16 {%0,%1,%2,%3}, [%4];"
        : "=r"(r0),"=r"(r1),"=r"(r2),"=r"(r3) : "r"(addr));
}
__device__ __forceinline__ void ldsm_x4_t(uint32_t& r0, uint32_t& r1, uint32_t& r2, uint32_t& r3, uint32_t addr){
    asm volatile("ldmatrix.sync.aligned.m8n8.x4.trans.shared.b16 {%0,%1,%2,%3}, [%4];"
        : "=r"(r0),"=r"(r1),"=r"(r2),"=r"(r3) : "r"(addr));
}
__device__ __forceinline__ void mma16816(float* c, uint32_t a0,uint32_t a1,uint32_t a2,uint32_t a3,
                                         uint32_t b0, uint32_t b1){
    asm volatile("mma.sync.aligned.m16n8k16.row.col.f32.f16.f16.f32 "
                 "{%0,%1,%2,%3},{%4,%5,%6,%7},{%8,%9},{%0,%1,%2,%3};"
        : "+f"(c[0]),"+f"(c[1]),"+f"(c[2]),"+f"(c[3])
        : "r"(a0),"r"(a1),"r"(a2),"r"(a3),"r"(b0),"r"(b1));
}

// ---------------- init: build fp16 weights [layer][r*64+k][o] + fused bias + zero cursors ----------------
__global__ void k_init(const float* __restrict__ Wl, const float* __restrict__ bl,
                       const float* __restrict__ Wr)
{
    for (int idx = blockIdx.x*blockDim.x + threadIdx.x; idx < 3*4*64*64; idx += gridDim.x*blockDim.x){
        int o = idx & 63;
        int k = (idx>>6) & 63;
        int r = (idx>>12) & 3;
        int l = idx>>14;
        float w;
        if (r < 3) w = Wl[(((size_t)l*3 + r)*64 + o)*64 + k];
        else       w = Wr[(((size_t)l*3 + 0)*64 + o)*64 + k]
                     + Wr[(((size_t)l*3 + 1)*64 + o)*64 + k]
                     + Wr[(((size_t)l*3 + 2)*64 + o)*64 + k];
        g_Wh[idx] = __float2half(w);
        if (idx < 3*64){
            int l2 = idx>>6, o2 = idx&63;
            g_bias[idx] = bl[(l2*3+0)*64+o2] + bl[(l2*3+1)*64+o2] + bl[(l2*3+2)*64+o2];
        }
    }
    for (int i = blockIdx.x*blockDim.x + threadIdx.x; i < NS; i += gridDim.x*blockDim.x){
        g_cur_ss[i]=0; g_cur_as[i]=0; g_cur_us[i]=0;
    }
}

// ---------------- fp32 -> fp16 conversion of node features ----------------
__global__ void k_convert(const float* __restrict__ xs, const float* __restrict__ xa,
                          const float* __restrict__ xu)
{
    int b = blockIdx.x;
    const float4* src; uint2* dst; int n4, b0, nb;
    if (b < 2048){ src=(const float4*)xs; dst=(uint2*)h_sub; n4=NS*16; b0=0;    nb=2048; }
    else if (b < 6144){ src=(const float4*)xa; dst=(uint2*)h_agr; n4=NA*16; b0=2048; nb=4096; }
    else { src=(const float4*)xu; dst=(uint2*)h_urb; n4=NU*16; b0=6144; nb=2048; }
    for (int i = (b-b0)*blockDim.x + threadIdx.x; i < n4; i += nb*blockDim.x){
        float4 v = __ldg(&src[i]);
        __half2 h0 = __floats2half2_rn(v.x, v.y);
        __half2 h1 = __floats2half2_rn(v.z, v.w);
        uint2 u;
        u.x = *(unsigned*)&h0;
        u.y = *(unsigned*)&h1;
        dst[i] = u;
    }
}

// ---------------- merged CSR count ----------------
__global__ void k_count_all(const int* __restrict__ d_ss, const int* __restrict__ d_as,
                            const int* __restrict__ d_us)
{
    int b = blockIdx.x;
    const int* dst; int E, b0, nb; int* cur;
    if (b < 2048){ dst=d_ss; E=ESS; b0=0;    nb=2048; cur=g_cur_ss; }
    else if (b < 6144){ dst=d_as; E=EAS; b0=2048; nb=4096; cur=g_cur_as; }
    else { dst=d_us; E=EUS; b0=6144; nb=2048; cur=g_cur_us; }
    for (int e = (b-b0)*blockDim.x + threadIdx.x; e < E; e += nb*blockDim.x)
        atomicAdd(&cur[__ldg(&dst[e])], 1);
}

// ---------------- merged scans ----------------
__global__ void k_scan_local_all()
{
    int rel = blockIdx.x / NB;
    int blk = blockIdx.x % NB;
    const int* deg = rel_cur(rel);
    int* off = rel_off(rel);
    int* part = g_part + rel*256;
    __shared__ int s[2][1024];
    int t = threadIdx.x;
    int i = blk*1024 + t;
    int v = (i < NS) ? deg[i] : 0;
    int pa = 0;
    s[0][t] = v;
    __syncthreads();
    #pragma unroll
    for (int d = 1; d < 1024; d <<= 1){
        int val = s[pa][t];
        if (t >= d) val += s[pa][t-d];
        s[pa^1][t] = val;
        pa ^= 1;
        __syncthreads();
    }
    int inc = s[pa][t];
    if (i < NS) off[i] = inc - v;        // block-local exclusive
    if (t == 1023) part[blk] = inc;
}

__global__ void k_scan_part_all()
{
    int rel = blockIdx.x;
    int* part = g_part + rel*256;
    int* off = rel_off(rel);
    __shared__ int ws[8];
    int t = threadIdx.x;
    int lane = t & 31, wid = t >> 5;
    int v = (t < NB) ? part[t] : 0;
    int x = v;
    #pragma unroll
    for (int d = 1; d < 32; d <<= 1){
        int y = __shfl_up_sync(0xffffffffu, x, d);
        if (lane >= d) x += y;
    }
    if (lane == 31) ws[wid] = x;
    __syncthreads();
    if (t == 0){
        int run = 0;
        #pragma unroll
        for (int i = 0; i < 8; i++){ int tmp = ws[i]; ws[i] = run; run += tmp; }
    }
    __syncthreads();
    x += ws[wid];
    if (t < NB) part[t] = x - v;         // exclusive partials
    if (t == 255) off[NS] = x;           // grand total
}

__global__ void k_scan_add_all()
{
    int rel = blockIdx.x / NB;
    int blk = blockIdx.x % NB;
    int* off = rel_off(rel);
    int* cur = rel_cur(rel);
    const int* part = g_part + rel*256;
    int i = blk*1024 + threadIdx.x;
    if (i < NS){
        int v = off[i] + part[blk];
        off[i] = v;
        cur[i] = v;       // cursor for fill
    }
}

// ---------------- merged fill ----------------
__global__ void k_fill_all(const int* __restrict__ ss_s, const int* __restrict__ ss_d,
                           const int* __restrict__ as_s, const int* __restrict__ as_d,
                           const int* __restrict__ us_s, const int* __restrict__ us_d)
{
    int b = blockIdx.x;
    const int* src; const int* dst; int E, b0, nb; int* cur; int* csr;
    if (b < 2048){ src=ss_s; dst=ss_d; E=ESS; b0=0;    nb=2048; cur=g_cur_ss; csr=g_csr_ss; }
    else if (b < 6144){ src=as_s; dst=as_d; E=EAS; b0=2048; nb=4096; cur=g_cur_as; csr=g_csr_as; }
    else { src=us_s; dst=us_d; E=EUS; b0=6144; nb=2048; cur=g_cur_us; csr=g_csr_us; }
    for (int e = (b-b0)*blockDim.x + threadIdx.x; e < E; e += nb*blockDim.x){
        int d = __ldg(&dst[e]);
        int p = atomicAdd(&cur[d], 1);
        csr[p] = __ldg(&src[e]);
    }
}

// ---------------- gather core (fp16 rows, fp32 accumulate, 4-way unrolled) ----------------
__device__ __forceinline__ void gather_sum_h(const __half2* __restrict__ x2,
                                             const int* __restrict__ csr,
                                             int b, int e, int lane,
                                             float& ax, float& ay)
{
    int i = b;
    for (; i + 4 <= e; i += 4){
        int s0 = __ldg(&csr[i]);
        int s1 = __ldg(&csr[i+1]);
        int s2 = __ldg(&csr[i+2]);
        int s3 = __ldg(&csr[i+3]);
        float2 f0 = __half22float2(__ldg(&x2[(size_t)s0*32 + lane]));
        float2 f1 = __half22float2(__ldg(&x2[(size_t)s1*32 + lane]));
        float2 f2 = __half22float2(__ldg(&x2[(size_t)s2*32 + lane]));
        float2 f3 = __half22float2(__ldg(&x2[(size_t)s3*32 + lane]));
        ax += (f0.x + f1.x) + (f2.x + f3.x);
        ay += (f0.y + f1.y) + (f2.y + f3.y);
    }
    for (; i < e; i++){
        int s0 = __ldg(&csr[i]);
        float2 f0 = __half22float2(__ldg(&x2[(size_t)s0*32 + lane]));
        ax += f0.x; ay += f0.y;
    }
}

// external-feature gather (sum): one warp per destination node; one relation per launch
__global__ void k_gather_ext(int rel, int outsel)
{
    int warp = (blockIdx.x*blockDim.x + threadIdx.x) >> 5;
    int lane = threadIdx.x & 31;
    if (warp >= NS) return;
    const __half* x = rel==0 ? h_sub : (rel==1 ? h_agr : h_urb);
    const int* csr = rel_csr(rel);
    const int* off = rel_off(rel);
    __half* op = outsel==0 ? g_agg_ss : (outsel==1 ? g_agg_as : g_agg_us);
    int b = __ldg(&off[warp]);
    int e = __ldg(&off[warp+1]);
    float ax = 0.f, ay = 0.f;
    gather_sum_h((const __half2*)x, csr, b, e, lane, ax, ay);
    ((__half2*)op)[(size_t)warp*32 + lane] = __floats2half2_rn(ax, ay);
}

// per-layer ss gather with mean (layers 1,2)
__global__ void k_gather_ss(int insel)
{
    const __half* x = insel==1 ? g_sub0 : g_sub1;
    int warp = (blockIdx.x*blockDim.x + threadIdx.x) >> 5;
    int lane = threadIdx.x & 31;
    if (warp >= NS) return;
    int b = __ldg(&g_off_ss[warp]);
    int e = __ldg(&g_off_ss[warp+1]);
    float ax = 0.f, ay = 0.f;
    gather_sum_h((const __half2*)x, g_csr_ss, b, e, lane, ax, ay);
    if (e > b){ float sc = 1.f/(float)(e-b); ax *= sc; ay *= sc; }
    ((__half2*)g_agg_ss)[(size_t)warp*32 + lane] = __floats2half2_rn(ax, ay);
}

// ---------------- fused layer GEMM on tensor cores (+ optional softmax head epilogue) ----------------
__global__ void __launch_bounds__(256,2)
k_gemm(int sub_sel, int out_sel, int layer,
       const float* __restrict__ Wf, const float* __restrict__ bf,
       float* __restrict__ outhead, int do_head)
{
    extern __shared__ char sm[];
    __half* Ws  = (__half*)(sm + SMEM_WS);
    __half* As  = (__half*)(sm + SMEM_AS);
    float*  Bs  = (float*)(sm + SMEM_BS);
    float*  Wfs = (float*)(sm + SMEM_WFS);
    float*  bfs = (float*)(sm + SMEM_BFS);

    const int tid  = threadIdx.x;
    const int lane = tid & 31;
    const int warp = tid >> 5;
    const int wm   = warp & 3;          // m-block: rows wm*16..+15
    const int wn   = warp >> 2;         // n-block: cols wn*32..+31

    // stage weights (once): g_Wh[layer][row][o] -> Ws[row][72]
    {
        const __half* wsrc = g_Wh + layer*16384;
        #pragma unroll
        for (int it = 0; it < 8; it++){
            int chunk = it*256 + tid;           // 2048 chunks of 8 halves
            int row = chunk >> 3, c = chunk & 7;
            *(uint4*)(Ws + row*72 + c*8) = *(const uint4*)(wsrc + row*64 + c*8);
        }
    }
    if (tid < 64) Bs[tid] = g_bias[layer*64 + tid];
    if (do_head){
        for (int j = tid; j < 384; j += 256) Wfs[j] = Wf[j];
        if (tid < 6) bfs[tid] = bf[tid];
    }

    const __half* Asub = sub_sel==0 ? h_sub : (sub_sel==1 ? g_sub0 : g_sub1);
    __half* outp = out_sel==0 ? g_sub0 : g_sub1;

    // per-lane ldmatrix address components
    const int l8  = lane & 7;
    const int grp = lane >> 3;
    const int row_off = l8 + ((grp & 1) << 3);      // 0..15
    const int col_off = (grp & 2) << 2;             // 0 or 8
    const uint32_t as_base = (uint32_t)__cvta_generic_to_shared(As);
    const uint32_t ws_base = (uint32_t)__cvta_generic_to_shared(Ws);
    const uint32_t uA0 = as_base + (wm*16 + row_off)*144 + col_off*2;
    const uint32_t uB0 = ws_base + row_off*144 + (wn*32 + col_off)*2;

    for (int tile = blockIdx.x; tile < GEMM_TILES; tile += gridDim.x){
        const int base = tile*64;

        __syncthreads();   // previous tile's As/Hs readers done (also covers Ws init on tile 0)
        // stage A: 4 relations x 64 rows x 64 halves
        #pragma unroll
        for (int r = 0; r < 4; r++){
            const __half* A = (r==0) ? g_agg_ss : (r==1) ? g_agg_as : (r==2) ? g_agg_us : Asub;
            #pragma unroll
            for (int it = 0; it < 2; it++){
                int chunk = it*256 + tid;       // 512 chunks of 8 halves
                int m = chunk >> 3, c = chunk & 7;
                *(uint4*)(As + (r*64 + m)*72 + c*8) =
                    *(const uint4*)(A + ((size_t)(base + m))*64 + c*8);
            }
        }
        __syncthreads();

        float c0[4], c1[4], c2[4], c3[4];
        #pragma unroll
        for (int t = 0; t < 4; t++){ c0[t]=0.f; c1[t]=0.f; c2[t]=0.f; c3[t]=0.f; }

        #pragma unroll
        for (int ks = 0; ks < 16; ks++){
            const int r  = ks >> 2;
            const int kk = (ks & 3) << 4;
            uint32_t a0,a1,a2,a3;
            ldsm_x4(a0,a1,a2,a3, uA0 + r*9216 + kk*2);
            uint32_t b0,b1,b2,b3, b4,b5,b6,b7;
            ldsm_x4_t(b0,b1,b2,b3, uB0 + ks*2304);          // n-cols wn*32 .. +15
            ldsm_x4_t(b4,b5,b6,b7, uB0 + ks*2304 + 32);     // n-cols wn*32+16 .. +31
            mma16816(c0, a0,a1,a2,a3, b0,b1);
            mma16816(c1, a0,a1,a2,a3, b2,b3);
            mma16816(c2, a0,a1,a2,a3, b4,b5);
            mma16816(c3, a0,a1,a2,a3, b6,b7);
        }

        const int mrow = wm*16 + (lane >> 2);
        const int ncol = wn*32 + ((lane & 3) << 1);
        float* cc[4] = {c0, c1, c2, c3};
        if (!do_head){
            #pragma unroll
            for (int t = 0; t < 4; t++){
                int col = ncol + t*8;
                float bb0 = Bs[col], bb1 = Bs[col+1];
                __half2 h0 = __floats2half2_rn(fmaxf(cc[t][0]+bb0,0.f), fmaxf(cc[t][1]+bb1,0.f));
                __half2 h1 = __floats2half2_rn(fmaxf(cc[t][2]+bb0,0.f), fmaxf(cc[t][3]+bb1,0.f));
                *(__half2*)(outp + ((size_t)(base+mrow  ))*64 + col) = h0;
                *(__half2*)(outp + ((size_t)(base+mrow+8))*64 + col) = h1;
            }
        } else {
            float* Hs = (float*)As;            // 64 nodes x stride 68
            __syncthreads();                   // all warps done reading As
            #pragma unroll
            for (int t = 0; t < 4; t++){
                int col = ncol + t*8;
                float bb0 = Bs[col], bb1 = Bs[col+1];
                Hs[(mrow  )*68 + col  ] = fmaxf(cc[t][0]+bb0,0.f);
                Hs[(mrow  )*68 + col+1] = fmaxf(cc[t][1]+bb1,0.f);
                Hs[(mrow+8)*68 + col  ] = fmaxf(cc[t][2]+bb0,0.f);
                Hs[(mrow+8)*68 + col+1] = fmaxf(cc[t][3]+bb1,0.f);
            }
            __syncthreads();
            int node = tid >> 2, q = tid & 3;  // 4 threads per node, 16 k each
            const float* hrow = Hs + node*68 + q*16;
            float p[6];
            #pragma unroll
            for (int o = 0; o < 6; o++) p[o] = 0.f;
            #pragma unroll
            for (int k = 0; k < 16; k++){
                float xv = hrow[k];
                #pragma unroll
                for (int o = 0; o < 6; o++) p[o] += xv * Wfs[o*64 + q*16 + k];
            }
            #pragma unroll
            for (int s = 1; s < 4; s <<= 1){
                #pragma unroll
                for (int o = 0; o < 6; o++) p[o] += __shfl_xor_sync(0xffffffffu, p[o], s);
            }
            if (q == 0){
                float m = -1e30f;
                #pragma unroll
                for (int o = 0; o < 6; o++){ p[o] += bfs[o]; m = fmaxf(m, p[o]); }
                float ssum = 0.f;
                #pragma unroll
                for (int o = 0; o < 6; o++){ p[o] = expf(p[o] - m); ssum += p[o]; }
                float inv = 1.f/ssum;
                float* op = outhead + (size_t)(base + node)*6;
                #pragma unroll
                for (int o = 0; o < 6; o++) op[o] = p[o]*inv;
            }
            // loop-top __syncthreads() protects Hs before next tile's As staging
        }
    }
}

// ---------------- launch ----------------
extern "C" void kernel_launch(void* const* d_in, const int* in_sizes, int n_in,
                              void* d_out, int out_size)
{
    const float* x_sub   = (const float*)d_in[0];
    const float* x_agr   = (const float*)d_in[1];
    const float* x_urb   = (const float*)d_in[2];
    const float* Wl      = (const float*)d_in[3];
    const float* bl      = (const float*)d_in[4];
    const float* Wr      = (const float*)d_in[5];
    const float* Wf      = (const float*)d_in[6];
    const float* bf      = (const float*)d_in[7];
    const int*   e_ss    = (const int*)d_in[8];
    const int*   e_as_s  = (const int*)d_in[9];
    const int*   e_as_d  = (const int*)d_in[10];
    const int*   e_us    = (const int*)d_in[11];
    float* out = (float*)d_out;

    cudaFuncSetAttribute(k_gemm, cudaFuncAttributeMaxDynamicSharedMemorySize, GEMM_SMEM);

    k_init<<<512,256>>>(Wl, bl, Wr);
    k_convert<<<8192,256>>>(x_sub, x_agr, x_urb);

    k_count_all<<<8192,256>>>(e_ss + ESS, e_as_d, e_us + EUS);

    k_scan_local_all<<<3*NB,1024>>>();
    k_scan_part_all<<<3,256>>>();
    k_scan_add_all<<<3*NB,1024>>>();

    k_fill_all<<<8192,256>>>(e_ss, e_ss + ESS, e_as_s, e_as_d, e_us, e_us + EUS);

    // layer-invariant aggregations, separate launches for L2 locality
    k_gather_ext<<<25000,256>>>(1, 1);
    k_gather_ext<<<25000,256>>>(2, 2);

    // layer 0: sum aggregation, sub input = h_sub, out -> g_sub0
    k_gather_ext<<<25000,256>>>(0, 0);
    k_gemm<<<296,256,GEMM_SMEM>>>(0, 0, 0, nullptr, nullptr, nullptr, 0);
    // layer 1: mean aggregation, sub input = g_sub0, out -> g_sub1
    k_gather_ss<<<25000,256>>>(1);
    k_gemm<<<296,256,GEMM_SMEM>>>(1, 1, 1, nullptr, nullptr, nullptr, 0);
    // layer 2: mean aggregation, sub input = g_sub1, head fused -> d_out
    k_gather_ss<<<25000,256>>>(2);
    k_gemm<<<296,256,GEMM_SMEM>>>(2, 0, 2, Wf, bf, out, 1);
}

// round 15
// speedup vs baseline: 1.4234x; 1.0418x over previous
#include <cuda_runtime.h>
#include <cuda_fp16.h>
#include <cstdint>

#define NS 200000
#define NA 400000
#define NU 200000
#define HH 64
#define ESS 2000000
#define EAS 4000000
#define EUS 2000000
#define GEMM_TILES 3125        // NS/64

#define PAD_SS 64
#define PAD_AS 96
#define PAD_US 64

// smem layout (bytes):
//   Ws  half[256][72]  36864   @ 0
//   As  half[256][72]  36864   @ 36864   (4 relations x 64 rows; aliased by Hs f32[64][68])
//   Bs  f32[64]          256   @ 73728
//   Wfs f32[384]        1536   @ 73984
//   bfs f32[8]            32   @ 75520
#define SMEM_WS   0
#define SMEM_AS   36864
#define SMEM_BS   73728
#define SMEM_WFS  73984
#define SMEM_BFS  75520
#define GEMM_SMEM 75552

typedef unsigned long long ull;

// ---------------- static device scratch (no allocations allowed) ----------------
__device__ __align__(256) __half h_sub[NS*HH];
__device__ __align__(256) __half h_agr[NA*HH];
__device__ __align__(256) __half h_urb[NU*HH];
__device__ __align__(256) __half g_agg_ss[NS*HH];
__device__ __align__(256) __half g_agg_as[NS*HH];
__device__ __align__(256) __half g_agg_us[NS*HH];
__device__ __align__(256) __half g_sub0[NS*HH];
__device__ __align__(256) __half g_sub1[NS*HH];
__device__ int g_pad_ss[(size_t)NS*PAD_SS];
__device__ int g_pad_as[(size_t)NS*PAD_AS];
__device__ int g_pad_us[(size_t)NS*PAD_US];
__device__ int g_cur_ss[NS];
__device__ int g_cur_as[NS];
__device__ int g_cur_us[NS];
__device__ __align__(16) __half g_Wh[3*4*HH*HH];   // [layer][r*64+k][o] fp16
__device__ float g_bias[3*HH];

__device__ __forceinline__ void ldsm_x4(uint32_t& r0, uint32_t& r1, uint32_t& r2, uint32_t& r3, uint32_t addr){
    asm volatile("ldmatrix.sync.aligned.m8n8.x4.shared.b16 {%0,%1,%2,%3}, [%4];"
        : "=r"(r0),"=r"(r1),"=r"(r2),"=r"(r3) : "r"(addr));
}
__device__ __forceinline__ void ldsm_x4_t(uint32_t& r0, uint32_t& r1, uint32_t& r2, uint32_t& r3, uint32_t addr){
    asm volatile("ldmatrix.sync.aligned.m8n8.x4.trans.shared.b16 {%0,%1,%2,%3}, [%4];"
        : "=r"(r0),"=r"(r1),"=r"(r2),"=r"(r3) : "r"(addr));
}
__device__ __forceinline__ void mma16816(float* c, uint32_t a0,uint32_t a1,uint32_t a2,uint32_t a3,
                                         uint32_t b0, uint32_t b1){
    asm volatile("mma.sync.aligned.m16n8k16.row.col.f32.f16.f16.f32 "
                 "{%0,%1,%2,%3},{%4,%5,%6,%7},{%8,%9},{%0,%1,%2,%3};"
        : "+f"(c[0]),"+f"(c[1]),"+f"(c[2]),"+f"(c[3])
        : "r"(a0),"r"(a1),"r"(a2),"r"(a3),"r"(b0),"r"(b1));
}

// ---------------- init: build fp16 weights [layer][r*64+k][o] + fused bias + zero cursors ----------------
__global__ void k_init(const float* __restrict__ Wl, const float* __restrict__ bl,
                       const float* __restrict__ Wr)
{
    for (int idx = blockIdx.x*blockDim.x + threadIdx.x; idx < 3*4*64*64; idx += gridDim.x*blockDim.x){
        int o = idx & 63;
        int k = (idx>>6) & 63;
        int r = (idx>>12) & 3;
        int l = idx>>14;
        float w;
        if (r < 3) w = Wl[(((size_t)l*3 + r)*64 + o)*64 + k];
        else       w = Wr[(((size_t)l*3 + 0)*64 + o)*64 + k]
                     + Wr[(((size_t)l*3 + 1)*64 + o)*64 + k]
                     + Wr[(((size_t)l*3 + 2)*64 + o)*64 + k];
        g_Wh[idx] = __float2half(w);
        if (idx < 3*64){
            int l2 = idx>>6, o2 = idx&63;
            g_bias[idx] = bl[(l2*3+0)*64+o2] + bl[(l2*3+1)*64+o2] + bl[(l2*3+2)*64+o2];
        }
    }
    for (int i = blockIdx.x*blockDim.x + threadIdx.x; i < NS; i += gridDim.x*blockDim.x){
        g_cur_ss[i]=0; g_cur_as[i]=0; g_cur_us[i]=0;
    }
}

// ---------------- fp32 -> fp16 conversion of node features ----------------
__global__ void k_convert(const float* __restrict__ xs, const float* __restrict__ xa,
                          const float* __restrict__ xu)
{
    int b = blockIdx.x;
    const float4* src; uint2* dst; int n4, b0, nb;
    if (b < 2048){ src=(const float4*)xs; dst=(uint2*)h_sub; n4=NS*16; b0=0;    nb=2048; }
    else if (b < 6144){ src=(const float4*)xa; dst=(uint2*)h_agr; n4=NA*16; b0=2048; nb=4096; }
    else { src=(const float4*)xu; dst=(uint2*)h_urb; n4=NU*16; b0=6144; nb=2048; }
    for (int i = (b-b0)*blockDim.x + threadIdx.x; i < n4; i += nb*blockDim.x){
        float4 v = __ldg(&src[i]);
        __half2 h0 = __floats2half2_rn(v.x, v.y);
        __half2 h1 = __floats2half2_rn(v.z, v.w);
        uint2 u;
        u.x = *(unsigned*)&h0;
        u.y = *(unsigned*)&h1;
        dst[i] = u;
    }
}

// ---------------- merged padded-CSR fill (atomic cursor = count + placement in one pass) ----------------
__global__ void k_fill_all(const int* __restrict__ ss_s, const int* __restrict__ ss_d,
                           const int* __restrict__ as_s, const int* __restrict__ as_d,
                           const int* __restrict__ us_s, const int* __restrict__ us_d)
{
    int b = blockIdx.x;
    const int* src; const int* dst; int E, b0, nb, pad; int* cur; int* csr;
    if (b < 2048){ src=ss_s; dst=ss_d; E=ESS; b0=0;    nb=2048; cur=g_cur_ss; csr=g_pad_ss; pad=PAD_SS; }
    else if (b < 6144){ src=as_s; dst=as_d; E=EAS; b0=2048; nb=4096; cur=g_cur_as; csr=g_pad_as; pad=PAD_AS; }
    else { src=us_s; dst=us_d; E=EUS; b0=6144; nb=2048; cur=g_cur_us; csr=g_pad_us; pad=PAD_US; }
    for (int e = (b-b0)*blockDim.x + threadIdx.x; e < E; e += nb*blockDim.x){
        int d = __ldg(&dst[e]);
        int p = atomicAdd(&cur[d], 1);
        csr[(size_t)d*pad + p] = __ldg(&src[e]);
    }
}

// ---------------- gather core (fp16 rows, fp32 accumulate, 4-way unrolled) ----------------
__device__ __forceinline__ void gather_sum_h(const __half2* __restrict__ x2,
                                             const int* __restrict__ csr,
                                             int deg, int lane,
                                             float& ax, float& ay)
{
    int i = 0;
    for (; i + 4 <= deg; i += 4){
        int s0 = __ldg(&csr[i]);
        int s1 = __ldg(&csr[i+1]);
        int s2 = __ldg(&csr[i+2]);
        int s3 = __ldg(&csr[i+3]);
        float2 f0 = __half22float2(__ldg(&x2[(size_t)s0*32 + lane]));
        float2 f1 = __half22float2(__ldg(&x2[(size_t)s1*32 + lane]));
        float2 f2 = __half22float2(__ldg(&x2[(size_t)s2*32 + lane]));
        float2 f3 = __half22float2(__ldg(&x2[(size_t)s3*32 + lane]));
        ax += (f0.x + f1.x) + (f2.x + f3.x);
        ay += (f0.y + f1.y) + (f2.y + f3.y);
    }
    for (; i < deg; i++){
        int s0 = __ldg(&csr[i]);
        float2 f0 = __half22float2(__ldg(&x2[(size_t)s0*32 + lane]));
        ax += f0.x; ay += f0.y;
    }
}

// external-feature gather (sum): one warp per destination node; one relation per launch
__global__ void k_gather_ext(int rel, int outsel)
{
    int warp = (blockIdx.x*blockDim.x + threadIdx.x) >> 5;
    int lane = threadIdx.x & 31;
    if (warp >= NS) return;
    const __half* x; const int* csr; const int* cur; int pad;
    if (rel==0){ x = h_sub; csr = g_pad_ss; cur = g_cur_ss; pad = PAD_SS; }
    else if (rel==1){ x = h_agr; csr = g_pad_as; cur = g_cur_as; pad = PAD_AS; }
    else { x = h_urb; csr = g_pad_us; cur = g_cur_us; pad = PAD_US; }
    __half* op = outsel==0 ? g_agg_ss : (outsel==1 ? g_agg_as : g_agg_us);
    int deg = __ldg(&cur[warp]);
    float ax = 0.f, ay = 0.f;
    gather_sum_h((const __half2*)x, csr + (size_t)warp*pad, deg, lane, ax, ay);
    ((__half2*)op)[(size_t)warp*32 + lane] = __floats2half2_rn(ax, ay);
}

// per-layer ss gather with mean (layers 1,2)
__global__ void k_gather_ss(int insel)
{
    const __half* x = insel==1 ? g_sub0 : g_sub1;
    int warp = (blockIdx.x*blockDim.x + threadIdx.x) >> 5;
    int lane = threadIdx.x & 31;
    if (warp >= NS) return;
    int deg = __ldg(&g_cur_ss[warp]);
    float ax = 0.f, ay = 0.f;
    gather_sum_h((const __half2*)x, g_pad_ss + (size_t)warp*PAD_SS, deg, lane, ax, ay);
    if (deg > 0){ float sc = 1.f/(float)deg; ax *= sc; ay *= sc; }
    ((__half2*)g_agg_ss)[(size_t)warp*32 + lane] = __floats2half2_rn(ax, ay);
}

// ---------------- fused layer GEMM on tensor cores (+ optional softmax head epilogue) ----------------
__global__ void __launch_bounds__(256,2)
k_gemm(int sub_sel, int out_sel, int layer,
       const float* __restrict__ Wf, const float* __restrict__ bf,
       float* __restrict__ outhead, int do_head)
{
    extern __shared__ char sm[];
    __half* Ws  = (__half*)(sm + SMEM_WS);
    __half* As  = (__half*)(sm + SMEM_AS);
    float*  Bs  = (float*)(sm + SMEM_BS);
    float*  Wfs = (float*)(sm + SMEM_WFS);
    float*  bfs = (float*)(sm + SMEM_BFS);

    const int tid  = threadIdx.x;
    const int lane = tid & 31;
    const int warp = tid >> 5;
    const int wm   = warp & 3;          // m-block: rows wm*16..+15
    const int wn   = warp >> 2;         // n-block: cols wn*32..+31

    // stage weights (once): g_Wh[layer][row][o] -> Ws[row][72]
    {
        const __half* wsrc = g_Wh + layer*16384;
        #pragma unroll
        for (int it = 0; it < 8; it++){
            int chunk = it*256 + tid;           // 2048 chunks of 8 halves
            int row = chunk >> 3, c = chunk & 7;
            *(uint4*)(Ws + row*72 + c*8) = *(const uint4*)(wsrc + row*64 + c*8);
        }
    }
    if (tid < 64) Bs[tid] = g_bias[layer*64 + tid];
    if (do_head){
        for (int j = tid; j < 384; j += 256) Wfs[j] = Wf[j];
        if (tid < 6) bfs[tid] = bf[tid];
    }

    const __half* Asub = sub_sel==0 ? h_sub : (sub_sel==1 ? g_sub0 : g_sub1);
    __half* outp = out_sel==0 ? g_sub0 : g_sub1;

    // per-lane ldmatrix address components
    const int l8  = lane & 7;
    const int grp = lane >> 3;
    const int row_off = l8 + ((grp & 1) << 3);      // 0..15
    const int col_off = (grp & 2) << 2;             // 0 or 8
    const uint32_t as_base = (uint32_t)__cvta_generic_to_shared(As);
    const uint32_t ws_base = (uint32_t)__cvta_generic_to_shared(Ws);
    const uint32_t uA0 = as_base + (wm*16 + row_off)*144 + col_off*2;
    const uint32_t uB0 = ws_base + row_off*144 + (wn*32 + col_off)*2;

    for (int tile = blockIdx.x; tile < GEMM_TILES; tile += gridDim.x){
        const int base = tile*64;

        __syncthreads();   // previous tile's As/Hs readers done (also covers Ws init on tile 0)
        // stage A: 4 relations x 64 rows x 64 halves
        #pragma unroll
        for (int r = 0; r < 4; r++){
            const __half* A = (r==0) ? g_agg_ss : (r==1) ? g_agg_as : (r==2) ? g_agg_us : Asub;
            #pragma unroll
            for (int it = 0; it < 2; it++){
                int chunk = it*256 + tid;       // 512 chunks of 8 halves
                int m = chunk >> 3, c = chunk & 7;
                *(uint4*)(As + (r*64 + m)*72 + c*8) =
                    *(const uint4*)(A + ((size_t)(base + m))*64 + c*8);
            }
        }
        __syncthreads();

        float c0[4], c1[4], c2[4], c3[4];
        #pragma unroll
        for (int t = 0; t < 4; t++){ c0[t]=0.f; c1[t]=0.f; c2[t]=0.f; c3[t]=0.f; }

        #pragma unroll
        for (int ks = 0; ks < 16; ks++){
            const int r  = ks >> 2;
            const int kk = (ks & 3) << 4;
            uint32_t a0,a1,a2,a3;
            ldsm_x4(a0,a1,a2,a3, uA0 + r*9216 + kk*2);
            uint32_t b0,b1,b2,b3, b4,b5,b6,b7;
            ldsm_x4_t(b0,b1,b2,b3, uB0 + ks*2304);          // n-cols wn*32 .. +15
            ldsm_x4_t(b4,b5,b6,b7, uB0 + ks*2304 + 32);     // n-cols wn*32+16 .. +31
            mma16816(c0, a0,a1,a2,a3, b0,b1);
            mma16816(c1, a0,a1,a2,a3, b2,b3);
            mma16816(c2, a0,a1,a2,a3, b4,b5);
            mma16816(c3, a0,a1,a2,a3, b6,b7);
        }

        const int mrow = wm*16 + (lane >> 2);
        const int ncol = wn*32 + ((lane & 3) << 1);
        float* cc[4] = {c0, c1, c2, c3};
        if (!do_head){
            #pragma unroll
            for (int t = 0; t < 4; t++){
                int col = ncol + t*8;
                float bb0 = Bs[col], bb1 = Bs[col+1];
                __half2 h0 = __floats2half2_rn(fmaxf(cc[t][0]+bb0,0.f), fmaxf(cc[t][1]+bb1,0.f));
                __half2 h1 = __floats2half2_rn(fmaxf(cc[t][2]+bb0,0.f), fmaxf(cc[t][3]+bb1,0.f));
                *(__half2*)(outp + ((size_t)(base+mrow  ))*64 + col) = h0;
                *(__half2*)(outp + ((size_t)(base+mrow+8))*64 + col) = h1;
            }
        } else {
            float* Hs = (float*)As;            // 64 nodes x stride 68
            __syncthreads();                   // all warps done reading As
            #pragma unroll
            for (int t = 0; t < 4; t++){
                int col = ncol + t*8;
                float bb0 = Bs[col], bb1 = Bs[col+1];
                Hs[(mrow  )*68 + col  ] = fmaxf(cc[t][0]+bb0,0.f);
                Hs[(mrow  )*68 + col+1] = fmaxf(cc[t][1]+bb1,0.f);
                Hs[(mrow+8)*68 + col  ] = fmaxf(cc[t][2]+bb0,0.f);
                Hs[(mrow+8)*68 + col+1] = fmaxf(cc[t][3]+bb1,0.f);
            }
            __syncthreads();
            int node = tid >> 2, q = tid & 3;  // 4 threads per node, 16 k each
            const float* hrow = Hs + node*68 + q*16;
            float p[6];
            #pragma unroll
            for (int o = 0; o < 6; o++) p[o] = 0.f;
            #pragma unroll
            for (int k = 0; k < 16; k++){
                float xv = hrow[k];
                #pragma unroll
                for (int o = 0; o < 6; o++) p[o] += xv * Wfs[o*64 + q*16 + k];
            }
            #pragma unroll
            for (int s = 1; s < 4; s <<= 1){
                #pragma unroll
                for (int o = 0; o < 6; o++) p[o] += __shfl_xor_sync(0xffffffffu, p[o], s);
            }
            if (q == 0){
                float m = -1e30f;
                #pragma unroll
                for (int o = 0; o < 6; o++){ p[o] += bfs[o]; m = fmaxf(m, p[o]); }
                float ssum = 0.f;
                #pragma unroll
                for (int o = 0; o < 6; o++){ p[o] = expf(p[o] - m); ssum += p[o]; }
                float inv = 1.f/ssum;
                float* op = outhead + (size_t)(base + node)*6;
                #pragma unroll
                for (int o = 0; o < 6; o++) op[o] = p[o]*inv;
            }
            // loop-top __syncthreads() protects Hs before next tile's As staging
        }
    }
}

// ---------------- launch ----------------
extern "C" void kernel_launch(void* const* d_in, const int* in_sizes, int n_in,
                              void* d_out, int out_size)
{
    const float* x_sub   = (const float*)d_in[0];
    const float* x_agr   = (const float*)d_in[1];
    const float* x_urb   = (const float*)d_in[2];
    const float* Wl      = (const float*)d_in[3];
    const float* bl      = (const float*)d_in[4];
    const float* Wr      = (const float*)d_in[5];
    const float* Wf      = (const float*)d_in[6];
    const float* bf      = (const float*)d_in[7];
    const int*   e_ss    = (const int*)d_in[8];
    const int*   e_as_s  = (const int*)d_in[9];
    const int*   e_as_d  = (const int*)d_in[10];
    const int*   e_us    = (const int*)d_in[11];
    float* out = (float*)d_out;

    cudaFuncSetAttribute(k_gemm, cudaFuncAttributeMaxDynamicSharedMemorySize, GEMM_SMEM);

    k_init<<<512,256>>>(Wl, bl, Wr);
    k_convert<<<8192,256>>>(x_sub, x_agr, x_urb);

    // single-pass padded-CSR build (replaces count + 3 scans + fill)
    k_fill_all<<<8192,256>>>(e_ss, e_ss + ESS, e_as_s, e_as_d, e_us, e_us + EUS);

    // layer-invariant aggregations, separate launches for L2 locality
    k_gather_ext<<<25000,256>>>(1, 1);
    k_gather_ext<<<25000,256>>>(2, 2);

    // layer 0: sum aggregation, sub input = h_sub, out -> g_sub0
    k_gather_ext<<<25000,256>>>(0, 0);
    k_gemm<<<296,256,GEMM_SMEM>>>(0, 0, 0, nullptr, nullptr, nullptr, 0);
    // layer 1: mean aggregation, sub input = g_sub0, out -> g_sub1
    k_gather_ss<<<25000,256>>>(1);
    k_gemm<<<296,256,GEMM_SMEM>>>(1, 1, 1, nullptr, nullptr, nullptr, 0);
    // layer 2: mean aggregation, sub input = g_sub1, head fused -> d_out
    k_gather_ss<<<25000,256>>>(2);
    k_gemm<<<296,256,GEMM_SMEM>>>(2, 0, 2, Wf, bf, out, 1);
}